// round 11
// baseline (speedup 1.0000x reference)
#include <cuda_runtime.h>
#include <cuda.h>
#include <cuda_fp16.h>
#include <cstdint>

// ============================================================================
// TernaryLinear: out[m,n] = sum_k x[m,k] * sign(w[n,k])
//   M = 8192, N = 16384, K = 4096, fp32 in/out.
//
// fp16 single-plane GEMM on legacy mma.sync (tcgen05 unavailable: harness
// emits plain compute_103 PTX). A = fp16(x), B = sign(w) exact in fp16,
// fp32 accumulation. rel_err ~2.1e-4 (verified rounds 4-10).
//
// Round-11 vs round 9 (best, 2.067 ms, tensor=91.0%; R10 peek REVERTED —
// its "memory"-clobbered probe broke the MMA interleave):
//   * 16 warps (512 thr), warp tile 32x64: 4 warps/SMSP so the arbiter
//     covers per-stage FULL-wait (90cyc fast path) and ldmatrix heads with
//     another warp's HMMAs. LDSM/MMA = 0.375 (R4's failed 16-warp config
//     was 0.5 and co-bound L1; 0.25 was R9) -> projected L1 ~73%, free.
//   * everything else R9-verbatim (ring, inline producer, early EMPTY).
// ============================================================================

#define M_TOTAL 8192
#define K_TOTAL 4096
#define N_TOTAL 16384

// ------------------------- device scratch (no mallocs) ---------------------
__device__ __align__(1024) __half g_A[(size_t)M_TOTAL * K_TOTAL];   // 64 MB
__device__ __align__(1024) __half g_B[(size_t)N_TOTAL * K_TOTAL];   // 128 MB

// ------------------------------ PTX helpers --------------------------------
__device__ __forceinline__ uint32_t smem_u32(const void* p) {
    uint32_t a;
    asm("{ .reg .u64 t; cvta.to.shared.u64 t, %1; cvt.u32.u64 %0, t; }"
        : "=r"(a) : "l"(p));
    return a;
}

#define MBAR_INIT(addr, cnt) \
    asm volatile("mbarrier.init.shared.b64 [%0], %1;" :: "r"(addr), "r"(cnt) : "memory")

#define MBAR_EXPECT_TX(addr, bytes) \
    asm volatile("mbarrier.arrive.expect_tx.shared.b64 _, [%0], %1;" \
                 :: "r"(addr), "r"(bytes) : "memory")

#define MBAR_ARRIVE(addr) \
    asm volatile("mbarrier.arrive.shared.b64 _, [%0];" :: "r"(addr) : "memory")

#define MBAR_WAIT(addr, ph) do {                                              \
    asm volatile("{\n\t.reg .pred P1;\n\t"                                    \
        "WAIT_%=:\n\t"                                                        \
        "mbarrier.try_wait.parity.acquire.cta.shared::cta.b64 P1, [%0], %1, 0x989680;\n\t" \
        "@P1 bra.uni DONE_%=;\n\t"                                            \
        "bra.uni WAIT_%=;\n\t"                                                \
        "DONE_%=:\n\t}"                                                       \
        :: "r"(addr), "r"(ph) : "memory");                                    \
} while (0)

// relaxed: post-wait accesses are async-proxy (TMA) only
#define MBAR_WAIT_RELAXED(addr, ph) do {                                      \
    asm volatile("{\n\t.reg .pred P1;\n\t"                                    \
        "WAIT_%=:\n\t"                                                        \
        "mbarrier.try_wait.parity.relaxed.cta.shared::cta.b64 P1, [%0], %1, 0x989680;\n\t" \
        "@P1 bra.uni DONE_%=;\n\t"                                            \
        "bra.uni WAIT_%=;\n\t"                                                \
        "DONE_%=:\n\t}"                                                       \
        :: "r"(addr), "r"(ph) : "memory");                                    \
} while (0)

#define TMA_LOAD_2D(dst, map, cx, cy, mbar) \
    asm volatile("cp.async.bulk.tensor.2d.shared::cta.global.tile.mbarrier::complete_tx::bytes " \
                 "[%0], [%1, {%2, %3}], [%4];" \
                 :: "r"(dst), "l"(map), "r"(cx), "r"(cy), "r"(mbar) : "memory")

#define FENCE_PROXY_ASYNC() \
    asm volatile("fence.proxy.async.shared::cta;" ::: "memory")

#define LDSM4(r0, r1, r2, r3, addr)                                           \
    asm volatile("ldmatrix.sync.aligned.m8n8.x4.shared.b16 {%0,%1,%2,%3}, [%4];" \
        : "=r"(r0), "=r"(r1), "=r"(r2), "=r"(r3) : "r"(addr))

#define MMA_F16(d, a, b0, b1)                                                 \
    asm volatile("mma.sync.aligned.m16n8k16.row.col.f32.f16.f16.f32 "         \
        "{%0,%1,%2,%3}, {%4,%5,%6,%7}, {%8,%9}, {%0,%1,%2,%3};"               \
        : "+f"((d)[0]), "+f"((d)[1]), "+f"((d)[2]), "+f"((d)[3])              \
        : "r"((a)[0]), "r"((a)[1]), "r"((a)[2]), "r"((a)[3]),                 \
          "r"(b0), "r"(b1))

// -------------------- fused prologue: x->fp16, sign(w)->fp16 ---------------
// sign() as fp16 bits: +1 = 0x3C00, -1 = 0xBC00, 0 = 0x0000
__device__ __forceinline__ uint32_t sgnh2(float a, float b) {
    uint32_t ua = __float_as_uint(a), ub = __float_as_uint(b);
    uint32_t ma = (a != 0.0f) ? 0x3C00u : 0u;
    uint32_t mb = (b != 0.0f) ? 0x3C00u : 0u;
    ma |= (ua >> 16) & 0x8000u;
    mb |= (ub >> 16) & 0x8000u;
    return ma | (mb << 16);
}

// one thread: 1 float4 of x (-> 8B of A) + 2 float4 of w (-> 16B of B)
__global__ void prep_kernel(const float4* __restrict__ x,
                            const float4* __restrict__ w, int n4x) {
    int i = blockIdx.x * blockDim.x + threadIdx.x;
    if (i >= n4x) return;

    float4 v = x[i];
    __half2 h0 = __floats2half2_rn(v.x, v.y);
    __half2 h1 = __floats2half2_rn(v.z, v.w);
    uint2 pa;
    pa.x = *reinterpret_cast<uint32_t*>(&h0);
    pa.y = *reinterpret_cast<uint32_t*>(&h1);
    reinterpret_cast<uint2*>(g_A)[i] = pa;

    float4 wa = w[2 * i];
    float4 wb = w[2 * i + 1];
    uint4 pb;
    pb.x = sgnh2(wa.x, wa.y);
    pb.y = sgnh2(wa.z, wa.w);
    pb.z = sgnh2(wb.x, wb.y);
    pb.w = sgnh2(wb.z, wb.w);
    reinterpret_cast<uint4*>(g_B)[i] = pb;
}

// ------------------------------- GEMM kernel -------------------------------
// CTA tile 256(M) x 128(N), K-step 64 halves (128 B rows). 4-stage TMA ring
// (48 KB/stage), FULL (tx) + EMPTY (16 warp arrivals) barriers.
// 512 threads = 16 warps (8x2); warp tile 32x64, 64 f32 accs / thread.
// Warp 0 lane 0 doubles as TMA producer (R6/R9-proven inline scheme).

static constexpr int STAGES      = 4;
static constexpr int A_STG       = 32768;           // 256 rows x 128 B
static constexpr int B_STG       = 16384;           // 128 rows x 128 B
static constexpr int STAGE_BYTES = A_STG + B_STG;   // 48 KB
static constexpr int KITERS      = K_TOTAL / 64;    // 64
static constexpr int SMEM_DYN    = 1024 + 1024 + STAGES * STAGE_BYTES;

__global__ void __launch_bounds__(512, 1) ternary_gemm_kernel(
    const __grid_constant__ CUtensorMap tma_a,
    const __grid_constant__ CUtensorMap tma_b,
    float* __restrict__ out)
{
    extern __shared__ uint8_t smem_raw[];
    const uint32_t sb    = smem_u32(smem_raw);
    const uint32_t base  = (sb + 1023u) & ~1023u;
    const uint32_t FULLB = base;          // 4 x 8B
    const uint32_t EMPTB = base + 64;     // 4 x 8B
    const uint32_t TILES = base + 1024;

    const int tid  = threadIdx.x;
    const int wid  = tid >> 5;
    const int lane = tid & 31;
    const int wm   = wid >> 1;            // 0..7  (M, 32-row tiles)
    const int wn   = wid & 1;             // 0..1  (N, 64-col tiles)

    // ---- tile mapping, GROUP_M=8 for L2 reuse ----
    constexpr int TILES_N = N_TOTAL / 128;   // 128
    constexpr int GROUP_M = 8;               // of 32 M-tiles
    const int per_group = GROUP_M * TILES_N;
    const int grp = blockIdx.x / per_group;
    const int ing = blockIdx.x % per_group;
    const int gm = (grp * GROUP_M + (ing % GROUP_M)) * 256;
    const int gn = (ing / GROUP_M) * 128;

    // ---- init barriers ----
    if (tid == 0) {
        #pragma unroll
        for (int s = 0; s < STAGES; s++) {
            MBAR_INIT(FULLB + 8 * s, 1);
            MBAR_INIT(EMPTB + 8 * s, 16);      // 16 warps arrive
        }
        FENCE_PROXY_ASYNC();
    }
    __syncthreads();   // only CTA-wide barrier in the kernel

    // ---- prologue: fill stages 0..STAGES-2 (first fills, no EMPTY wait) ----
    if (tid == 0) {
        #pragma unroll
        for (int s = 0; s < STAGES - 1; s++) {
            MBAR_EXPECT_TX(FULLB + 8 * s, (uint32_t)STAGE_BYTES);
            const uint32_t tb = TILES + s * STAGE_BYTES;
            TMA_LOAD_2D(tb,         &tma_a, s * 64, gm, FULLB + 8 * s);
            TMA_LOAD_2D(tb + A_STG, &tma_b, s * 64, gn, FULLB + 8 * s);
        }
    }

    // ---- per-lane ldmatrix address pieces (SW128 layout, verified R2-R10) --
    const int mi  = lane >> 3;
    const int r   = lane & 7;
    const int hi2 = mi >> 1;
    const uint32_t a_row_off = (uint32_t)(wm * 32 + (mi & 1) * 8 + r) * 128;
    const uint32_t b_row_off = (uint32_t)(wn * 64 + hi2 * 8 + r) * 128;

    // ---- accumulators: [mt(2)][nt(8)][4] f32 = 64 regs ----
    float acc[2][8][4];
    #pragma unroll
    for (int a = 0; a < 2; a++)
        #pragma unroll
        for (int b = 0; b < 8; b++)
            #pragma unroll
            for (int c = 0; c < 4; c++) acc[a][b][c] = 0.0f;

    // ---- main loop ----
    for (int kt = 0; kt < KITERS; kt++) {
        const int s = kt & (STAGES - 1);
        const uint32_t full_ph = (uint32_t)((kt >> 2) & 1);
        MBAR_WAIT(FULLB + 8 * s, full_ph);

        const uint32_t sa  = TILES + s * STAGE_BYTES;
        const uint32_t sbb = sa + A_STG;

        #pragma unroll
        for (int kc = 0; kc < 4; kc++) {   // 4 x k16 per 128B chunk
            const uint32_t ax = (uint32_t)((((kc << 1) | hi2) ^ r) << 4);
            const uint32_t bx = (uint32_t)((((kc << 1) | (mi & 1)) ^ r) << 4);

            uint32_t af[2][4], bf[8][2];
            #pragma unroll
            for (int mt = 0; mt < 2; mt++)
                LDSM4(af[mt][0], af[mt][1], af[mt][2], af[mt][3],
                      sa + a_row_off + mt * 2048 + ax);
            #pragma unroll
            for (int j = 0; j < 4; j++)
                LDSM4(bf[2 * j][0], bf[2 * j][1], bf[2 * j + 1][0], bf[2 * j + 1][1],
                      sbb + b_row_off + j * 2048 + bx);

            // stage data fully in registers after the last ldmatrix
            if (kc == 3 && lane == 0) MBAR_ARRIVE(EMPTB + 8 * s);

            #pragma unroll
            for (int mt = 0; mt < 2; mt++)
                #pragma unroll
                for (int nt = 0; nt < 8; nt++)
                    MMA_F16(acc[mt][nt], af[mt], bf[nt][0], bf[nt][1]);
        }

        // refill stage for iteration kt+STAGES-1 (after compute: 2-stage slack)
        if (tid == 0 && kt + STAGES - 1 < KITERS) {
            const int f  = kt + STAGES - 1;
            const int ns = f & (STAGES - 1);
            const int n  = f >> 2;                     // fill instance
            if (n >= 1)
                MBAR_WAIT_RELAXED(EMPTB + 8 * ns, (uint32_t)((n - 1) & 1));
            MBAR_EXPECT_TX(FULLB + 8 * ns, (uint32_t)STAGE_BYTES);
            const uint32_t tb = TILES + ns * STAGE_BYTES;
            const int kx = f * 64;
            TMA_LOAD_2D(tb,         &tma_a, kx, gm, FULLB + 8 * ns);
            TMA_LOAD_2D(tb + A_STG, &tma_b, kx, gn, FULLB + 8 * ns);
        }
    }

    // ---- epilogue ----
    const int rbase = gm + wm * 32 + (lane >> 2);
    const int cbase = gn + wn * 64 + (lane & 3) * 2;
    #pragma unroll
    for (int mt = 0; mt < 2; mt++) {
        const int r0 = rbase + mt * 16;
        #pragma unroll
        for (int nt = 0; nt < 8; nt++) {
            const int c = cbase + nt * 8;
            float2 v;
            v.x = acc[mt][nt][0];
            v.y = acc[mt][nt][1];
            *reinterpret_cast<float2*>(out + (size_t)r0 * N_TOTAL + c) = v;
            v.x = acc[mt][nt][2];
            v.y = acc[mt][nt][3];
            *reinterpret_cast<float2*>(out + (size_t)(r0 + 8) * N_TOTAL + c) = v;
        }
    }
}

// ------------------------------- host side ---------------------------------
typedef CUresult (*encode_fn_t)(CUtensorMap*, CUtensorMapDataType, cuuint32_t,
                                void*, const cuuint64_t*, const cuuint64_t*,
                                const cuuint32_t*, const cuuint32_t*,
                                CUtensorMapInterleave, CUtensorMapSwizzle,
                                CUtensorMapL2promotion, CUtensorMapFloatOOBfill);

static void make_map_f16(CUtensorMap* m, void* ptr,
                         uint64_t inner, uint64_t outer,
                         uint32_t box_i, uint32_t box_o) {
    encode_fn_t fn = nullptr;
    cudaDriverEntryPointQueryResult st;
    cudaGetDriverEntryPointByVersion("cuTensorMapEncodeTiled", (void**)&fn,
                                     12000, cudaEnableDefault, &st);
    if (!fn) return;
    cuuint64_t dims[2]    = {inner, outer};
    cuuint64_t strides[1] = {inner * 2};      // bytes (fp16)
    cuuint32_t box[2]     = {box_i, box_o};
    cuuint32_t es[2]      = {1, 1};
    fn(m, CU_TENSOR_MAP_DATA_TYPE_UINT16, 2, ptr, dims, strides, box, es,
       CU_TENSOR_MAP_INTERLEAVE_NONE, CU_TENSOR_MAP_SWIZZLE_128B,
       CU_TENSOR_MAP_L2_PROMOTION_L2_128B, CU_TENSOR_MAP_FLOAT_OOB_FILL_NONE);
}

extern "C" void kernel_launch(void* const* d_in, const int* in_sizes, int n_in,
                              void* d_out, int out_size) {
    const float* x = (const float*)d_in[0];   // [2,4096,4096]
    const float* w = (const float*)d_in[1];   // [16384,4096]
    float* out = (float*)d_out;               // [2,4096,16384]

    // fused prologue (1 launch so ncu -s5 -c1 lands on the GEMM)
    {
        const int n4x = (M_TOTAL * K_TOTAL) / 4;
        prep_kernel<<<(n4x + 255) / 256, 256>>>((const float4*)x,
                                                (const float4*)w, n4x);
    }

    void *p_a = nullptr, *p_b = nullptr;
    cudaGetSymbolAddress(&p_a, g_A);
    cudaGetSymbolAddress(&p_b, g_B);

    CUtensorMap mA, mB;
    make_map_f16(&mA, p_a, K_TOTAL, M_TOTAL, 64, 256);
    make_map_f16(&mB, p_b, K_TOTAL, N_TOTAL, 64, 128);

    cudaFuncSetAttribute(ternary_gemm_kernel,
                         cudaFuncAttributeMaxDynamicSharedMemorySize, SMEM_DYN);

    const int grid = (M_TOTAL / 256) * (N_TOTAL / 128);   // 4096
    ternary_gemm_kernel<<<grid, 512, SMEM_DYN>>>(mA, mB, out);
}

// round 12
// speedup vs baseline: 1.0627x; 1.0627x over previous
#include <cuda_runtime.h>
#include <cuda.h>
#include <cuda_fp16.h>
#include <cstdint>

// ============================================================================
// TernaryLinear: out[m,n] = sum_k x[m,k] * sign(w[n,k])
//   M = 8192, N = 16384, K = 4096, fp32 in/out.
//
// fp16 single-plane GEMM on legacy mma.sync (tcgen05 unavailable: harness
// emits plain compute_103 PTX). A = fp16(x), B = sign(w) exact in fp16,
// fp32 accumulation. rel_err ~2.1e-4 (verified rounds 4-11).
//
// Round-12 vs round 9 (best, 2.067 ms, tensor=91.0%). R10 (peek) and R11
// (16 warps) both regressed -> residual ~9% idle is IN-WARP dependency
// exposure. This round: explicit fragment DOUBLE-BUFFERING in the k-chunk
// loop — LDSMs for chunk kc+1 issue while MMAs consume chunk kc, removing
// the ~30cyc ldmatrix head from the critical path. Backbone = R9 verbatim.
// ============================================================================

#define M_TOTAL 8192
#define K_TOTAL 4096
#define N_TOTAL 16384

// ------------------------- device scratch (no mallocs) ---------------------
__device__ __align__(1024) __half g_A[(size_t)M_TOTAL * K_TOTAL];   // 64 MB
__device__ __align__(1024) __half g_B[(size_t)N_TOTAL * K_TOTAL];   // 128 MB

// ------------------------------ PTX helpers --------------------------------
__device__ __forceinline__ uint32_t smem_u32(const void* p) {
    uint32_t a;
    asm("{ .reg .u64 t; cvta.to.shared.u64 t, %1; cvt.u32.u64 %0, t; }"
        : "=r"(a) : "l"(p));
    return a;
}

#define MBAR_INIT(addr, cnt) \
    asm volatile("mbarrier.init.shared.b64 [%0], %1;" :: "r"(addr), "r"(cnt) : "memory")

#define MBAR_EXPECT_TX(addr, bytes) \
    asm volatile("mbarrier.arrive.expect_tx.shared.b64 _, [%0], %1;" \
                 :: "r"(addr), "r"(bytes) : "memory")

#define MBAR_ARRIVE(addr) \
    asm volatile("mbarrier.arrive.shared.b64 _, [%0];" :: "r"(addr) : "memory")

#define MBAR_WAIT(addr, ph) do {                                              \
    asm volatile("{\n\t.reg .pred P1;\n\t"                                    \
        "WAIT_%=:\n\t"                                                        \
        "mbarrier.try_wait.parity.acquire.cta.shared::cta.b64 P1, [%0], %1, 0x989680;\n\t" \
        "@P1 bra.uni DONE_%=;\n\t"                                            \
        "bra.uni WAIT_%=;\n\t"                                                \
        "DONE_%=:\n\t}"                                                       \
        :: "r"(addr), "r"(ph) : "memory");                                    \
} while (0)

// relaxed: post-wait accesses are async-proxy (TMA) only
#define MBAR_WAIT_RELAXED(addr, ph) do {                                      \
    asm volatile("{\n\t.reg .pred P1;\n\t"                                    \
        "WAIT_%=:\n\t"                                                        \
        "mbarrier.try_wait.parity.relaxed.cta.shared::cta.b64 P1, [%0], %1, 0x989680;\n\t" \
        "@P1 bra.uni DONE_%=;\n\t"                                            \
        "bra.uni WAIT_%=;\n\t"                                                \
        "DONE_%=:\n\t}"                                                       \
        :: "r"(addr), "r"(ph) : "memory");                                    \
} while (0)

#define TMA_LOAD_2D(dst, map, cx, cy, mbar) \
    asm volatile("cp.async.bulk.tensor.2d.shared::cta.global.tile.mbarrier::complete_tx::bytes " \
                 "[%0], [%1, {%2, %3}], [%4];" \
                 :: "r"(dst), "l"(map), "r"(cx), "r"(cy), "r"(mbar) : "memory")

#define FENCE_PROXY_ASYNC() \
    asm volatile("fence.proxy.async.shared::cta;" ::: "memory")

#define LDSM4(r0, r1, r2, r3, addr)                                           \
    asm volatile("ldmatrix.sync.aligned.m8n8.x4.shared.b16 {%0,%1,%2,%3}, [%4];" \
        : "=r"(r0), "=r"(r1), "=r"(r2), "=r"(r3) : "r"(addr))

#define MMA_F16(d, a, b0, b1)                                                 \
    asm volatile("mma.sync.aligned.m16n8k16.row.col.f32.f16.f16.f32 "         \
        "{%0,%1,%2,%3}, {%4,%5,%6,%7}, {%8,%9}, {%0,%1,%2,%3};"               \
        : "+f"((d)[0]), "+f"((d)[1]), "+f"((d)[2]), "+f"((d)[3])              \
        : "r"((a)[0]), "r"((a)[1]), "r"((a)[2]), "r"((a)[3]),                 \
          "r"(b0), "r"(b1))

// -------------------- fused prologue: x->fp16, sign(w)->fp16 ---------------
// sign() as fp16 bits: +1 = 0x3C00, -1 = 0xBC00, 0 = 0x0000
__device__ __forceinline__ uint32_t sgnh2(float a, float b) {
    uint32_t ua = __float_as_uint(a), ub = __float_as_uint(b);
    uint32_t ma = (a != 0.0f) ? 0x3C00u : 0u;
    uint32_t mb = (b != 0.0f) ? 0x3C00u : 0u;
    ma |= (ua >> 16) & 0x8000u;
    mb |= (ub >> 16) & 0x8000u;
    return ma | (mb << 16);
}

// one thread: 1 float4 of x (-> 8B of A) + 2 float4 of w (-> 16B of B)
__global__ void prep_kernel(const float4* __restrict__ x,
                            const float4* __restrict__ w, int n4x) {
    int i = blockIdx.x * blockDim.x + threadIdx.x;
    if (i >= n4x) return;

    float4 v = x[i];
    __half2 h0 = __floats2half2_rn(v.x, v.y);
    __half2 h1 = __floats2half2_rn(v.z, v.w);
    uint2 pa;
    pa.x = *reinterpret_cast<uint32_t*>(&h0);
    pa.y = *reinterpret_cast<uint32_t*>(&h1);
    reinterpret_cast<uint2*>(g_A)[i] = pa;

    float4 wa = w[2 * i];
    float4 wb = w[2 * i + 1];
    uint4 pb;
    pb.x = sgnh2(wa.x, wa.y);
    pb.y = sgnh2(wa.z, wa.w);
    pb.z = sgnh2(wb.x, wb.y);
    pb.w = sgnh2(wb.z, wb.w);
    reinterpret_cast<uint4*>(g_B)[i] = pb;
}

// ------------------------------- GEMM kernel -------------------------------
// CTA tile 256(M) x 128(N), K-step 64 halves (128 B rows). 4-stage TMA ring
// (48 KB/stage), FULL (tx) + EMPTY (8 warp arrivals) barriers.
// 256 threads = 8 warps (4x2); warp tile 64x64, 128 f32 accs / thread.
// Warp 0 lane 0 doubles as TMA producer. Fragments double-buffered.

static constexpr int STAGES      = 4;
static constexpr int A_STG       = 32768;           // 256 rows x 128 B
static constexpr int B_STG       = 16384;           // 128 rows x 128 B
static constexpr int STAGE_BYTES = A_STG + B_STG;   // 48 KB
static constexpr int KITERS      = K_TOTAL / 64;    // 64
static constexpr int SMEM_DYN    = 1024 + 1024 + STAGES * STAGE_BYTES;

__global__ void __launch_bounds__(256, 1) ternary_gemm_kernel(
    const __grid_constant__ CUtensorMap tma_a,
    const __grid_constant__ CUtensorMap tma_b,
    float* __restrict__ out)
{
    extern __shared__ uint8_t smem_raw[];
    const uint32_t sb    = smem_u32(smem_raw);
    const uint32_t base  = (sb + 1023u) & ~1023u;
    const uint32_t FULLB = base;          // 4 x 8B
    const uint32_t EMPTB = base + 64;     // 4 x 8B
    const uint32_t TILES = base + 1024;

    const int tid  = threadIdx.x;
    const int wid  = tid >> 5;
    const int lane = tid & 31;
    const int wm   = wid >> 1;            // 0..3  (M)
    const int wn   = wid & 1;             // 0..1  (N)

    // ---- tile mapping, GROUP_M=8 for L2 reuse ----
    constexpr int TILES_N = N_TOTAL / 128;   // 128
    constexpr int GROUP_M = 8;               // of 32 M-tiles
    const int per_group = GROUP_M * TILES_N;
    const int grp = blockIdx.x / per_group;
    const int ing = blockIdx.x % per_group;
    const int gm = (grp * GROUP_M + (ing % GROUP_M)) * 256;
    const int gn = (ing / GROUP_M) * 128;

    // ---- init barriers ----
    if (tid == 0) {
        #pragma unroll
        for (int s = 0; s < STAGES; s++) {
            MBAR_INIT(FULLB + 8 * s, 1);
            MBAR_INIT(EMPTB + 8 * s, 8);       // 8 warps arrive
        }
        FENCE_PROXY_ASYNC();
    }
    __syncthreads();   // only CTA-wide barrier in the kernel

    // ---- prologue: fill stages 0..STAGES-2 (first fills, no EMPTY wait) ----
    if (tid == 0) {
        #pragma unroll
        for (int s = 0; s < STAGES - 1; s++) {
            MBAR_EXPECT_TX(FULLB + 8 * s, (uint32_t)STAGE_BYTES);
            const uint32_t tb = TILES + s * STAGE_BYTES;
            TMA_LOAD_2D(tb,         &tma_a, s * 64, gm, FULLB + 8 * s);
            TMA_LOAD_2D(tb + A_STG, &tma_b, s * 64, gn, FULLB + 8 * s);
        }
    }

    // ---- per-lane ldmatrix address pieces (SW128 layout, verified R2-R11) --
    const int mi  = lane >> 3;
    const int r   = lane & 7;
    const int hi2 = mi >> 1;
    const uint32_t a_row_off = (uint32_t)(wm * 64 + (mi & 1) * 8 + r) * 128;
    const uint32_t b_row_off = (uint32_t)(wn * 64 + hi2 * 8 + r) * 128;

    // fragment loader for one k16 chunk into buffer bb
    #define LOAD_FRAGS(bb, sa_, sbb_, kcv) do {                               \
        const uint32_t ax_ = (uint32_t)(((((kcv) << 1) | hi2) ^ r) << 4);     \
        const uint32_t bx_ = (uint32_t)(((((kcv) << 1) | (mi & 1)) ^ r) << 4);\
        _Pragma("unroll")                                                     \
        for (int mt = 0; mt < 4; mt++)                                        \
            LDSM4(af[bb][mt][0], af[bb][mt][1], af[bb][mt][2], af[bb][mt][3], \
                  (sa_) + a_row_off + mt * 2048 + ax_);                       \
        _Pragma("unroll")                                                     \
        for (int j = 0; j < 4; j++)                                           \
            LDSM4(bf[bb][2*j][0], bf[bb][2*j][1],                             \
                  bf[bb][2*j+1][0], bf[bb][2*j+1][1],                         \
                  (sbb_) + b_row_off + j * 2048 + bx_);                       \
    } while (0)

    // ---- accumulators: [mt(4)][nt(8)][4] f32 = 128 regs ----
    float acc[4][8][4];
    #pragma unroll
    for (int a = 0; a < 4; a++)
        #pragma unroll
        for (int b = 0; b < 8; b++)
            #pragma unroll
            for (int c = 0; c < 4; c++) acc[a][b][c] = 0.0f;

    // ---- double-buffered fragments: 2 x (16 + 16) = 64 regs ----
    uint32_t af[2][4][4], bf[2][8][2];

    // ---- main loop ----
    for (int kt = 0; kt < KITERS; kt++) {
        const int s = kt & (STAGES - 1);
        const uint32_t full_ph = (uint32_t)((kt >> 2) & 1);
        MBAR_WAIT(FULLB + 8 * s, full_ph);

        const uint32_t sa  = TILES + s * STAGE_BYTES;
        const uint32_t sbb = sa + A_STG;

        // prime chunk 0 into buffer 0
        LOAD_FRAGS(0, sa, sbb, 0);

        #pragma unroll
        for (int kc = 0; kc < 4; kc++) {   // 4 x k16 per 128B chunk
            const int cb = kc & 1;
            // issue next chunk's LDSMs before consuming current fragments
            if (kc < 3) {
                const int nb = cb ^ 1;
                LOAD_FRAGS(nb, sa, sbb, kc + 1);
            } else if (lane == 0) {
                // stage fully read (last LDSMs already issued): free slot
                MBAR_ARRIVE(EMPTB + 8 * s);
            }

            #pragma unroll
            for (int mt = 0; mt < 4; mt++)
                #pragma unroll
                for (int nt = 0; nt < 8; nt++)
                    MMA_F16(acc[mt][nt], af[cb][mt], bf[cb][nt][0], bf[cb][nt][1]);
        }

        // refill stage for iteration kt+STAGES-1 (after compute: 2-stage slack)
        if (tid == 0 && kt + STAGES - 1 < KITERS) {
            const int f  = kt + STAGES - 1;
            const int ns = f & (STAGES - 1);
            const int n  = f >> 2;                     // fill instance
            if (n >= 1)
                MBAR_WAIT_RELAXED(EMPTB + 8 * ns, (uint32_t)((n - 1) & 1));
            MBAR_EXPECT_TX(FULLB + 8 * ns, (uint32_t)STAGE_BYTES);
            const uint32_t tb = TILES + ns * STAGE_BYTES;
            const int kx = f * 64;
            TMA_LOAD_2D(tb,         &tma_a, kx, gm, FULLB + 8 * ns);
            TMA_LOAD_2D(tb + A_STG, &tma_b, kx, gn, FULLB + 8 * ns);
        }
    }
    #undef LOAD_FRAGS

    // ---- epilogue ----
    const int rbase = gm + wm * 64 + (lane >> 2);
    const int cbase = gn + wn * 64 + (lane & 3) * 2;
    #pragma unroll
    for (int mt = 0; mt < 4; mt++) {
        const int r0 = rbase + mt * 16;
        #pragma unroll
        for (int nt = 0; nt < 8; nt++) {
            const int c = cbase + nt * 8;
            float2 v;
            v.x = acc[mt][nt][0];
            v.y = acc[mt][nt][1];
            *reinterpret_cast<float2*>(out + (size_t)r0 * N_TOTAL + c) = v;
            v.x = acc[mt][nt][2];
            v.y = acc[mt][nt][3];
            *reinterpret_cast<float2*>(out + (size_t)(r0 + 8) * N_TOTAL + c) = v;
        }
    }
}

// ------------------------------- host side ---------------------------------
typedef CUresult (*encode_fn_t)(CUtensorMap*, CUtensorMapDataType, cuuint32_t,
                                void*, const cuuint64_t*, const cuuint64_t*,
                                const cuuint32_t*, const cuuint32_t*,
                                CUtensorMapInterleave, CUtensorMapSwizzle,
                                CUtensorMapL2promotion, CUtensorMapFloatOOBfill);

static void make_map_f16(CUtensorMap* m, void* ptr,
                         uint64_t inner, uint64_t outer,
                         uint32_t box_i, uint32_t box_o) {
    encode_fn_t fn = nullptr;
    cudaDriverEntryPointQueryResult st;
    cudaGetDriverEntryPointByVersion("cuTensorMapEncodeTiled", (void**)&fn,
                                     12000, cudaEnableDefault, &st);
    if (!fn) return;
    cuuint64_t dims[2]    = {inner, outer};
    cuuint64_t strides[1] = {inner * 2};      // bytes (fp16)
    cuuint32_t box[2]     = {box_i, box_o};
    cuuint32_t es[2]      = {1, 1};
    fn(m, CU_TENSOR_MAP_DATA_TYPE_UINT16, 2, ptr, dims, strides, box, es,
       CU_TENSOR_MAP_INTERLEAVE_NONE, CU_TENSOR_MAP_SWIZZLE_128B,
       CU_TENSOR_MAP_L2_PROMOTION_L2_128B, CU_TENSOR_MAP_FLOAT_OOB_FILL_NONE);
}

extern "C" void kernel_launch(void* const* d_in, const int* in_sizes, int n_in,
                              void* d_out, int out_size) {
    const float* x = (const float*)d_in[0];   // [2,4096,4096]
    const float* w = (const float*)d_in[1];   // [16384,4096]
    float* out = (float*)d_out;               // [2,4096,16384]

    // fused prologue (1 launch so ncu -s5 -c1 lands on the GEMM)
    {
        const int n4x = (M_TOTAL * K_TOTAL) / 4;
        prep_kernel<<<(n4x + 255) / 256, 256>>>((const float4*)x,
                                                (const float4*)w, n4x);
    }

    void *p_a = nullptr, *p_b = nullptr;
    cudaGetSymbolAddress(&p_a, g_A);
    cudaGetSymbolAddress(&p_b, g_B);

    CUtensorMap mA, mB;
    make_map_f16(&mA, p_a, K_TOTAL, M_TOTAL, 64, 256);
    make_map_f16(&mB, p_b, K_TOTAL, N_TOTAL, 64, 128);

    cudaFuncSetAttribute(ternary_gemm_kernel,
                         cudaFuncAttributeMaxDynamicSharedMemorySize, SMEM_DYN);

    const int grid = (M_TOTAL / 256) * (N_TOTAL / 128);   // 4096
    ternary_gemm_kernel<<<grid, 256, SMEM_DYN>>>(mA, mB, out);
}

// round 13
// speedup vs baseline: 1.0672x; 1.0043x over previous
#include <cuda_runtime.h>
#include <cuda.h>
#include <cuda_fp16.h>
#include <cstdint>

// ============================================================================
// TernaryLinear: out[m,n] = sum_k x[m,k] * sign(w[n,k])
//   M = 8192, N = 16384, K = 4096, fp32 in/out.
//
// fp16 single-plane GEMM on legacy mma.sync (tcgen05 unavailable: harness
// emits plain compute_103 PTX). A = fp16(x), B = sign(w) exact in fp16,
// fp32 accumulation. rel_err ~2.1e-4 (verified rounds 4-12).
//
// Round-13 vs round 9/12 (best, 2.067 ms, tensor=91.0%): the residual ~9%
// is per-wave fill + epilogue drain exposed by occ=1 CTA/SM. This round:
// 2 CTAs/SM — CTA 128x128, 128 threads (4 warps of 64x64, SAME warp tile,
// SAME 0.25 LDSM/MMA, still 2 warps/SMSP), 3-stage 32KB ring (100KB smem,
// 55K regs -> both fit twice). Co-resident CTAs decorrelate after wave 1,
// so one CTA's epilogue/waits overlap the other's MMAs.
// ============================================================================

#define M_TOTAL 8192
#define K_TOTAL 4096
#define N_TOTAL 16384

// ------------------------- device scratch (no mallocs) ---------------------
__device__ __align__(1024) __half g_A[(size_t)M_TOTAL * K_TOTAL];   // 64 MB
__device__ __align__(1024) __half g_B[(size_t)N_TOTAL * K_TOTAL];   // 128 MB

// ------------------------------ PTX helpers --------------------------------
__device__ __forceinline__ uint32_t smem_u32(const void* p) {
    uint32_t a;
    asm("{ .reg .u64 t; cvta.to.shared.u64 t, %1; cvt.u32.u64 %0, t; }"
        : "=r"(a) : "l"(p));
    return a;
}

#define MBAR_INIT(addr, cnt) \
    asm volatile("mbarrier.init.shared.b64 [%0], %1;" :: "r"(addr), "r"(cnt) : "memory")

#define MBAR_EXPECT_TX(addr, bytes) \
    asm volatile("mbarrier.arrive.expect_tx.shared.b64 _, [%0], %1;" \
                 :: "r"(addr), "r"(bytes) : "memory")

#define MBAR_ARRIVE(addr) \
    asm volatile("mbarrier.arrive.shared.b64 _, [%0];" :: "r"(addr) : "memory")

#define MBAR_WAIT(addr, ph) do {                                              \
    asm volatile("{\n\t.reg .pred P1;\n\t"                                    \
        "WAIT_%=:\n\t"                                                        \
        "mbarrier.try_wait.parity.acquire.cta.shared::cta.b64 P1, [%0], %1, 0x989680;\n\t" \
        "@P1 bra.uni DONE_%=;\n\t"                                            \
        "bra.uni WAIT_%=;\n\t"                                                \
        "DONE_%=:\n\t}"                                                       \
        :: "r"(addr), "r"(ph) : "memory");                                    \
} while (0)

// relaxed: post-wait accesses are async-proxy (TMA) only
#define MBAR_WAIT_RELAXED(addr, ph) do {                                      \
    asm volatile("{\n\t.reg .pred P1;\n\t"                                    \
        "WAIT_%=:\n\t"                                                        \
        "mbarrier.try_wait.parity.relaxed.cta.shared::cta.b64 P1, [%0], %1, 0x989680;\n\t" \
        "@P1 bra.uni DONE_%=;\n\t"                                            \
        "bra.uni WAIT_%=;\n\t"                                                \
        "DONE_%=:\n\t}"                                                       \
        :: "r"(addr), "r"(ph) : "memory");                                    \
} while (0)

#define TMA_LOAD_2D(dst, map, cx, cy, mbar) \
    asm volatile("cp.async.bulk.tensor.2d.shared::cta.global.tile.mbarrier::complete_tx::bytes " \
                 "[%0], [%1, {%2, %3}], [%4];" \
                 :: "r"(dst), "l"(map), "r"(cx), "r"(cy), "r"(mbar) : "memory")

#define FENCE_PROXY_ASYNC() \
    asm volatile("fence.proxy.async.shared::cta;" ::: "memory")

#define LDSM4(r0, r1, r2, r3, addr)                                           \
    asm volatile("ldmatrix.sync.aligned.m8n8.x4.shared.b16 {%0,%1,%2,%3}, [%4];" \
        : "=r"(r0), "=r"(r1), "=r"(r2), "=r"(r3) : "r"(addr))

#define MMA_F16(d, a, b0, b1)                                                 \
    asm volatile("mma.sync.aligned.m16n8k16.row.col.f32.f16.f16.f32 "         \
        "{%0,%1,%2,%3}, {%4,%5,%6,%7}, {%8,%9}, {%0,%1,%2,%3};"               \
        : "+f"((d)[0]), "+f"((d)[1]), "+f"((d)[2]), "+f"((d)[3])              \
        : "r"((a)[0]), "r"((a)[1]), "r"((a)[2]), "r"((a)[3]),                 \
          "r"(b0), "r"(b1))

// -------------------- fused prologue: x->fp16, sign(w)->fp16 ---------------
// sign() as fp16 bits: +1 = 0x3C00, -1 = 0xBC00, 0 = 0x0000
__device__ __forceinline__ uint32_t sgnh2(float a, float b) {
    uint32_t ua = __float_as_uint(a), ub = __float_as_uint(b);
    uint32_t ma = (a != 0.0f) ? 0x3C00u : 0u;
    uint32_t mb = (b != 0.0f) ? 0x3C00u : 0u;
    ma |= (ua >> 16) & 0x8000u;
    mb |= (ub >> 16) & 0x8000u;
    return ma | (mb << 16);
}

// one thread: 1 float4 of x (-> 8B of A) + 2 float4 of w (-> 16B of B)
__global__ void prep_kernel(const float4* __restrict__ x,
                            const float4* __restrict__ w, int n4x) {
    int i = blockIdx.x * blockDim.x + threadIdx.x;
    if (i >= n4x) return;

    float4 v = x[i];
    __half2 h0 = __floats2half2_rn(v.x, v.y);
    __half2 h1 = __floats2half2_rn(v.z, v.w);
    uint2 pa;
    pa.x = *reinterpret_cast<uint32_t*>(&h0);
    pa.y = *reinterpret_cast<uint32_t*>(&h1);
    reinterpret_cast<uint2*>(g_A)[i] = pa;

    float4 wa = w[2 * i];
    float4 wb = w[2 * i + 1];
    uint4 pb;
    pb.x = sgnh2(wa.x, wa.y);
    pb.y = sgnh2(wa.z, wa.w);
    pb.z = sgnh2(wb.x, wb.y);
    pb.w = sgnh2(wb.z, wb.w);
    reinterpret_cast<uint4*>(g_B)[i] = pb;
}

// ------------------------------- GEMM kernel -------------------------------
// CTA tile 128(M) x 128(N), K-step 64 halves (128 B rows). 3-stage TMA ring
// (32 KB/stage), FULL (tx) + EMPTY (4 warp arrivals) barriers.
// 128 threads = 4 warps (2x2); warp tile 64x64, 128 f32 accs / thread.
// 2 CTAs per SM (smem 100KB, regs ~55K per CTA pair half).

static constexpr int STAGES      = 3;
static constexpr int A_STG       = 16384;           // 128 rows x 128 B
static constexpr int B_STG       = 16384;           // 128 rows x 128 B
static constexpr int STAGE_BYTES = A_STG + B_STG;   // 32 KB
static constexpr int KITERS      = K_TOTAL / 64;    // 64
static constexpr int SMEM_DYN    = 1024 + 1024 + STAGES * STAGE_BYTES;  // ~100KB

__global__ void __launch_bounds__(128, 2) ternary_gemm_kernel(
    const __grid_constant__ CUtensorMap tma_a,
    const __grid_constant__ CUtensorMap tma_b,
    float* __restrict__ out)
{
    extern __shared__ uint8_t smem_raw[];
    const uint32_t sb    = smem_u32(smem_raw);
    const uint32_t base  = (sb + 1023u) & ~1023u;
    const uint32_t FULLB = base;          // 3 x 8B
    const uint32_t EMPTB = base + 64;     // 3 x 8B
    const uint32_t TILES = base + 1024;

    const int tid  = threadIdx.x;
    const int wid  = tid >> 5;
    const int lane = tid & 31;
    const int wm   = wid >> 1;            // 0..1  (M)
    const int wn   = wid & 1;             // 0..1  (N)

    // ---- tile mapping, GROUP_M=16 for L2 reuse (same A-span as R9) ----
    constexpr int TILES_N = N_TOTAL / 128;   // 128
    constexpr int GROUP_M = 16;              // of 64 M-tiles
    const int per_group = GROUP_M * TILES_N;
    const int grp = blockIdx.x / per_group;
    const int ing = blockIdx.x % per_group;
    const int gm = (grp * GROUP_M + (ing % GROUP_M)) * 128;
    const int gn = (ing / GROUP_M) * 128;

    // ---- init barriers ----
    if (tid == 0) {
        #pragma unroll
        for (int s = 0; s < STAGES; s++) {
            MBAR_INIT(FULLB + 8 * s, 1);
            MBAR_INIT(EMPTB + 8 * s, 4);       // 4 warps arrive
        }
        FENCE_PROXY_ASYNC();
    }
    __syncthreads();   // only CTA-wide barrier in the kernel

    // ---- prologue: fill stages 0..1 (first fills, no EMPTY wait) ----
    if (tid == 0) {
        #pragma unroll
        for (int s = 0; s < STAGES - 1; s++) {
            MBAR_EXPECT_TX(FULLB + 8 * s, (uint32_t)STAGE_BYTES);
            const uint32_t tb = TILES + s * STAGE_BYTES;
            TMA_LOAD_2D(tb,         &tma_a, s * 64, gm, FULLB + 8 * s);
            TMA_LOAD_2D(tb + A_STG, &tma_b, s * 64, gn, FULLB + 8 * s);
        }
    }

    // ---- per-lane ldmatrix address pieces (SW128 layout, verified R2-R12) --
    const int mi  = lane >> 3;
    const int r   = lane & 7;
    const int hi2 = mi >> 1;
    const uint32_t a_row_off = (uint32_t)(wm * 64 + (mi & 1) * 8 + r) * 128;
    const uint32_t b_row_off = (uint32_t)(wn * 64 + hi2 * 8 + r) * 128;

    // ---- accumulators: [mt(4)][nt(8)][4] f32 = 128 regs ----
    float acc[4][8][4];
    #pragma unroll
    for (int a = 0; a < 4; a++)
        #pragma unroll
        for (int b = 0; b < 8; b++)
            #pragma unroll
            for (int c = 0; c < 4; c++) acc[a][b][c] = 0.0f;

    // ---- main loop (stage cursor: modulo-3 wrap) ----
    int cs = 0;                 // consumer stage
    uint32_t cph = 0;           // consumer phase

    for (int kt = 0; kt < KITERS; kt++) {
        MBAR_WAIT(FULLB + 8 * cs, cph);

        const uint32_t sa  = TILES + cs * STAGE_BYTES;
        const uint32_t sbb = sa + A_STG;

        #pragma unroll
        for (int kc = 0; kc < 4; kc++) {   // 4 x k16 per 128B chunk
            const uint32_t ax = (uint32_t)((((kc << 1) | hi2) ^ r) << 4);
            const uint32_t bx = (uint32_t)((((kc << 1) | (mi & 1)) ^ r) << 4);

            uint32_t af[4][4], bf[8][2];
            #pragma unroll
            for (int mt = 0; mt < 4; mt++)
                LDSM4(af[mt][0], af[mt][1], af[mt][2], af[mt][3],
                      sa + a_row_off + mt * 2048 + ax);
            #pragma unroll
            for (int j = 0; j < 4; j++)
                LDSM4(bf[2 * j][0], bf[2 * j][1], bf[2 * j + 1][0], bf[2 * j + 1][1],
                      sbb + b_row_off + j * 2048 + bx);

            // stage data fully in registers after the last ldmatrix
            if (kc == 3 && lane == 0) MBAR_ARRIVE(EMPTB + 8 * cs);

            #pragma unroll
            for (int mt = 0; mt < 4; mt++)
                #pragma unroll
                for (int nt = 0; nt < 8; nt++)
                    MMA_F16(acc[mt][nt], af[mt], bf[nt][0], bf[nt][1]);
        }

        // refill stage for iteration kt+2 (after compute: 1-stage slack)
        if (tid == 0 && kt + STAGES - 1 < KITERS) {
            const int f  = kt + STAGES - 1;
            const int n  = f / 3;                      // fill instance
            const int ns = f - n * 3;                  // f % 3
            if (n >= 1)
                MBAR_WAIT_RELAXED(EMPTB + 8 * ns, (uint32_t)((n - 1) & 1));
            MBAR_EXPECT_TX(FULLB + 8 * ns, (uint32_t)STAGE_BYTES);
            const uint32_t tb = TILES + ns * STAGE_BYTES;
            const int kx = f * 64;
            TMA_LOAD_2D(tb,         &tma_a, kx, gm, FULLB + 8 * ns);
            TMA_LOAD_2D(tb + A_STG, &tma_b, kx, gn, FULLB + 8 * ns);
        }

        if (++cs == STAGES) { cs = 0; cph ^= 1; }
    }

    // ---- epilogue ----
    const int rbase = gm + wm * 64 + (lane >> 2);
    const int cbase = gn + wn * 64 + (lane & 3) * 2;
    #pragma unroll
    for (int mt = 0; mt < 4; mt++) {
        const int r0 = rbase + mt * 16;
        #pragma unroll
        for (int nt = 0; nt < 8; nt++) {
            const int c = cbase + nt * 8;
            float2 v;
            v.x = acc[mt][nt][0];
            v.y = acc[mt][nt][1];
            *reinterpret_cast<float2*>(out + (size_t)r0 * N_TOTAL + c) = v;
            v.x = acc[mt][nt][2];
            v.y = acc[mt][nt][3];
            *reinterpret_cast<float2*>(out + (size_t)(r0 + 8) * N_TOTAL + c) = v;
        }
    }
}

// ------------------------------- host side ---------------------------------
typedef CUresult (*encode_fn_t)(CUtensorMap*, CUtensorMapDataType, cuuint32_t,
                                void*, const cuuint64_t*, const cuuint64_t*,
                                const cuuint32_t*, const cuuint32_t*,
                                CUtensorMapInterleave, CUtensorMapSwizzle,
                                CUtensorMapL2promotion, CUtensorMapFloatOOBfill);

static void make_map_f16(CUtensorMap* m, void* ptr,
                         uint64_t inner, uint64_t outer,
                         uint32_t box_i, uint32_t box_o) {
    encode_fn_t fn = nullptr;
    cudaDriverEntryPointQueryResult st;
    cudaGetDriverEntryPointByVersion("cuTensorMapEncodeTiled", (void**)&fn,
                                     12000, cudaEnableDefault, &st);
    if (!fn) return;
    cuuint64_t dims[2]    = {inner, outer};
    cuuint64_t strides[1] = {inner * 2};      // bytes (fp16)
    cuuint32_t box[2]     = {box_i, box_o};
    cuuint32_t es[2]      = {1, 1};
    fn(m, CU_TENSOR_MAP_DATA_TYPE_UINT16, 2, ptr, dims, strides, box, es,
       CU_TENSOR_MAP_INTERLEAVE_NONE, CU_TENSOR_MAP_SWIZZLE_128B,
       CU_TENSOR_MAP_L2_PROMOTION_L2_128B, CU_TENSOR_MAP_FLOAT_OOB_FILL_NONE);
}

extern "C" void kernel_launch(void* const* d_in, const int* in_sizes, int n_in,
                              void* d_out, int out_size) {
    const float* x = (const float*)d_in[0];   // [2,4096,4096]
    const float* w = (const float*)d_in[1];   // [16384,4096]
    float* out = (float*)d_out;               // [2,4096,16384]

    // fused prologue (1 launch so ncu -s5 -c1 lands on the GEMM)
    {
        const int n4x = (M_TOTAL * K_TOTAL) / 4;
        prep_kernel<<<(n4x + 255) / 256, 256>>>((const float4*)x,
                                                (const float4*)w, n4x);
    }

    void *p_a = nullptr, *p_b = nullptr;
    cudaGetSymbolAddress(&p_a, g_A);
    cudaGetSymbolAddress(&p_b, g_B);

    CUtensorMap mA, mB;
    make_map_f16(&mA, p_a, K_TOTAL, M_TOTAL, 64, 128);
    make_map_f16(&mB, p_b, K_TOTAL, N_TOTAL, 64, 128);

    cudaFuncSetAttribute(ternary_gemm_kernel,
                         cudaFuncAttributeMaxDynamicSharedMemorySize, SMEM_DYN);

    const int grid = (M_TOTAL / 128) * (N_TOTAL / 128);   // 64 * 128 = 8192
    ternary_gemm_kernel<<<grid, 128, SMEM_DYN>>>(mA, mB, out);
}

// round 14
// speedup vs baseline: 1.0682x; 1.0009x over previous
#include <cuda_runtime.h>
#include <cuda.h>
#include <cuda_fp16.h>
#include <cstdint>

// ============================================================================
// TernaryLinear: out[m,n] = sum_k x[m,k] * sign(w[n,k])
//   M = 8192, N = 16384, K = 4096, fp32 in/out.
//
// fp16 single-plane GEMM on legacy mma.sync (tcgen05 unavailable: harness
// emits plain compute_103 PTX). A = fp16(x), B = sign(w) exact in fp16,
// fp32 accumulation. rel_err ~2.1e-4 (verified rounds 4-13).
//
// Round-14 vs round 13 (best, 2.058 ms, tensor=91.4%, 2 CTA/SM):
//   * epilogue stores use st.global.cs (evict-first streaming): the 512 MB
//     of zero-reuse output no longer evicts A/B tiles from L2 during the
//     partner CTA's mainloop. Only change — everything else R13 verbatim.
// ============================================================================

#define M_TOTAL 8192
#define K_TOTAL 4096
#define N_TOTAL 16384

// ------------------------- device scratch (no mallocs) ---------------------
__device__ __align__(1024) __half g_A[(size_t)M_TOTAL * K_TOTAL];   // 64 MB
__device__ __align__(1024) __half g_B[(size_t)N_TOTAL * K_TOTAL];   // 128 MB

// ------------------------------ PTX helpers --------------------------------
__device__ __forceinline__ uint32_t smem_u32(const void* p) {
    uint32_t a;
    asm("{ .reg .u64 t; cvta.to.shared.u64 t, %1; cvt.u32.u64 %0, t; }"
        : "=r"(a) : "l"(p));
    return a;
}

#define MBAR_INIT(addr, cnt) \
    asm volatile("mbarrier.init.shared.b64 [%0], %1;" :: "r"(addr), "r"(cnt) : "memory")

#define MBAR_EXPECT_TX(addr, bytes) \
    asm volatile("mbarrier.arrive.expect_tx.shared.b64 _, [%0], %1;" \
                 :: "r"(addr), "r"(bytes) : "memory")

#define MBAR_ARRIVE(addr) \
    asm volatile("mbarrier.arrive.shared.b64 _, [%0];" :: "r"(addr) : "memory")

#define MBAR_WAIT(addr, ph) do {                                              \
    asm volatile("{\n\t.reg .pred P1;\n\t"                                    \
        "WAIT_%=:\n\t"                                                        \
        "mbarrier.try_wait.parity.acquire.cta.shared::cta.b64 P1, [%0], %1, 0x989680;\n\t" \
        "@P1 bra.uni DONE_%=;\n\t"                                            \
        "bra.uni WAIT_%=;\n\t"                                                \
        "DONE_%=:\n\t}"                                                       \
        :: "r"(addr), "r"(ph) : "memory");                                    \
} while (0)

// relaxed: post-wait accesses are async-proxy (TMA) only
#define MBAR_WAIT_RELAXED(addr, ph) do {                                      \
    asm volatile("{\n\t.reg .pred P1;\n\t"                                    \
        "WAIT_%=:\n\t"                                                        \
        "mbarrier.try_wait.parity.relaxed.cta.shared::cta.b64 P1, [%0], %1, 0x989680;\n\t" \
        "@P1 bra.uni DONE_%=;\n\t"                                            \
        "bra.uni WAIT_%=;\n\t"                                                \
        "DONE_%=:\n\t}"                                                       \
        :: "r"(addr), "r"(ph) : "memory");                                    \
} while (0)

#define TMA_LOAD_2D(dst, map, cx, cy, mbar) \
    asm volatile("cp.async.bulk.tensor.2d.shared::cta.global.tile.mbarrier::complete_tx::bytes " \
                 "[%0], [%1, {%2, %3}], [%4];" \
                 :: "r"(dst), "l"(map), "r"(cx), "r"(cy), "r"(mbar) : "memory")

#define FENCE_PROXY_ASYNC() \
    asm volatile("fence.proxy.async.shared::cta;" ::: "memory")

#define LDSM4(r0, r1, r2, r3, addr)                                           \
    asm volatile("ldmatrix.sync.aligned.m8n8.x4.shared.b16 {%0,%1,%2,%3}, [%4];" \
        : "=r"(r0), "=r"(r1), "=r"(r2), "=r"(r3) : "r"(addr))

#define MMA_F16(d, a, b0, b1)                                                 \
    asm volatile("mma.sync.aligned.m16n8k16.row.col.f32.f16.f16.f32 "         \
        "{%0,%1,%2,%3}, {%4,%5,%6,%7}, {%8,%9}, {%0,%1,%2,%3};"               \
        : "+f"((d)[0]), "+f"((d)[1]), "+f"((d)[2]), "+f"((d)[3])              \
        : "r"((a)[0]), "r"((a)[1]), "r"((a)[2]), "r"((a)[3]),                 \
          "r"(b0), "r"(b1))

// streaming (evict-first) 8-byte store
#define STG_CS_V2(ptr, v0, v1) \
    asm volatile("st.global.cs.v2.f32 [%0], {%1, %2};" \
                 :: "l"(ptr), "f"(v0), "f"(v1) : "memory")

// -------------------- fused prologue: x->fp16, sign(w)->fp16 ---------------
// sign() as fp16 bits: +1 = 0x3C00, -1 = 0xBC00, 0 = 0x0000
__device__ __forceinline__ uint32_t sgnh2(float a, float b) {
    uint32_t ua = __float_as_uint(a), ub = __float_as_uint(b);
    uint32_t ma = (a != 0.0f) ? 0x3C00u : 0u;
    uint32_t mb = (b != 0.0f) ? 0x3C00u : 0u;
    ma |= (ua >> 16) & 0x8000u;
    mb |= (ub >> 16) & 0x8000u;
    return ma | (mb << 16);
}

// one thread: 1 float4 of x (-> 8B of A) + 2 float4 of w (-> 16B of B)
__global__ void prep_kernel(const float4* __restrict__ x,
                            const float4* __restrict__ w, int n4x) {
    int i = blockIdx.x * blockDim.x + threadIdx.x;
    if (i >= n4x) return;

    float4 v = x[i];
    __half2 h0 = __floats2half2_rn(v.x, v.y);
    __half2 h1 = __floats2half2_rn(v.z, v.w);
    uint2 pa;
    pa.x = *reinterpret_cast<uint32_t*>(&h0);
    pa.y = *reinterpret_cast<uint32_t*>(&h1);
    reinterpret_cast<uint2*>(g_A)[i] = pa;

    float4 wa = w[2 * i];
    float4 wb = w[2 * i + 1];
    uint4 pb;
    pb.x = sgnh2(wa.x, wa.y);
    pb.y = sgnh2(wa.z, wa.w);
    pb.z = sgnh2(wb.x, wb.y);
    pb.w = sgnh2(wb.z, wb.w);
    reinterpret_cast<uint4*>(g_B)[i] = pb;
}

// ------------------------------- GEMM kernel -------------------------------
// CTA tile 128(M) x 128(N), K-step 64 halves (128 B rows). 3-stage TMA ring
// (32 KB/stage), FULL (tx) + EMPTY (4 warp arrivals) barriers.
// 128 threads = 4 warps (2x2); warp tile 64x64, 128 f32 accs / thread.
// 2 CTAs per SM.

static constexpr int STAGES      = 3;
static constexpr int A_STG       = 16384;           // 128 rows x 128 B
static constexpr int B_STG       = 16384;           // 128 rows x 128 B
static constexpr int STAGE_BYTES = A_STG + B_STG;   // 32 KB
static constexpr int KITERS      = K_TOTAL / 64;    // 64
static constexpr int SMEM_DYN    = 1024 + 1024 + STAGES * STAGE_BYTES;  // ~100KB

__global__ void __launch_bounds__(128, 2) ternary_gemm_kernel(
    const __grid_constant__ CUtensorMap tma_a,
    const __grid_constant__ CUtensorMap tma_b,
    float* __restrict__ out)
{
    extern __shared__ uint8_t smem_raw[];
    const uint32_t sb    = smem_u32(smem_raw);
    const uint32_t base  = (sb + 1023u) & ~1023u;
    const uint32_t FULLB = base;          // 3 x 8B
    const uint32_t EMPTB = base + 64;     // 3 x 8B
    const uint32_t TILES = base + 1024;

    const int tid  = threadIdx.x;
    const int wid  = tid >> 5;
    const int lane = tid & 31;
    const int wm   = wid >> 1;            // 0..1  (M)
    const int wn   = wid & 1;             // 0..1  (N)

    // ---- tile mapping, GROUP_M=16 for L2 reuse ----
    constexpr int TILES_N = N_TOTAL / 128;   // 128
    constexpr int GROUP_M = 16;              // of 64 M-tiles
    const int per_group = GROUP_M * TILES_N;
    const int grp = blockIdx.x / per_group;
    const int ing = blockIdx.x % per_group;
    const int gm = (grp * GROUP_M + (ing % GROUP_M)) * 128;
    const int gn = (ing / GROUP_M) * 128;

    // ---- init barriers ----
    if (tid == 0) {
        #pragma unroll
        for (int s = 0; s < STAGES; s++) {
            MBAR_INIT(FULLB + 8 * s, 1);
            MBAR_INIT(EMPTB + 8 * s, 4);       // 4 warps arrive
        }
        FENCE_PROXY_ASYNC();
    }
    __syncthreads();   // only CTA-wide barrier in the kernel

    // ---- prologue: fill stages 0..1 (first fills, no EMPTY wait) ----
    if (tid == 0) {
        #pragma unroll
        for (int s = 0; s < STAGES - 1; s++) {
            MBAR_EXPECT_TX(FULLB + 8 * s, (uint32_t)STAGE_BYTES);
            const uint32_t tb = TILES + s * STAGE_BYTES;
            TMA_LOAD_2D(tb,         &tma_a, s * 64, gm, FULLB + 8 * s);
            TMA_LOAD_2D(tb + A_STG, &tma_b, s * 64, gn, FULLB + 8 * s);
        }
    }

    // ---- per-lane ldmatrix address pieces (SW128 layout, verified R2-R13) --
    const int mi  = lane >> 3;
    const int r   = lane & 7;
    const int hi2 = mi >> 1;
    const uint32_t a_row_off = (uint32_t)(wm * 64 + (mi & 1) * 8 + r) * 128;
    const uint32_t b_row_off = (uint32_t)(wn * 64 + hi2 * 8 + r) * 128;

    // ---- accumulators: [mt(4)][nt(8)][4] f32 = 128 regs ----
    float acc[4][8][4];
    #pragma unroll
    for (int a = 0; a < 4; a++)
        #pragma unroll
        for (int b = 0; b < 8; b++)
            #pragma unroll
            for (int c = 0; c < 4; c++) acc[a][b][c] = 0.0f;

    // ---- main loop (stage cursor: modulo-3 wrap) ----
    int cs = 0;                 // consumer stage
    uint32_t cph = 0;           // consumer phase

    for (int kt = 0; kt < KITERS; kt++) {
        MBAR_WAIT(FULLB + 8 * cs, cph);

        const uint32_t sa  = TILES + cs * STAGE_BYTES;
        const uint32_t sbb = sa + A_STG;

        #pragma unroll
        for (int kc = 0; kc < 4; kc++) {   // 4 x k16 per 128B chunk
            const uint32_t ax = (uint32_t)((((kc << 1) | hi2) ^ r) << 4);
            const uint32_t bx = (uint32_t)((((kc << 1) | (mi & 1)) ^ r) << 4);

            uint32_t af[4][4], bf[8][2];
            #pragma unroll
            for (int mt = 0; mt < 4; mt++)
                LDSM4(af[mt][0], af[mt][1], af[mt][2], af[mt][3],
                      sa + a_row_off + mt * 2048 + ax);
            #pragma unroll
            for (int j = 0; j < 4; j++)
                LDSM4(bf[2 * j][0], bf[2 * j][1], bf[2 * j + 1][0], bf[2 * j + 1][1],
                      sbb + b_row_off + j * 2048 + bx);

            // stage data fully in registers after the last ldmatrix
            if (kc == 3 && lane == 0) MBAR_ARRIVE(EMPTB + 8 * cs);

            #pragma unroll
            for (int mt = 0; mt < 4; mt++)
                #pragma unroll
                for (int nt = 0; nt < 8; nt++)
                    MMA_F16(acc[mt][nt], af[mt], bf[nt][0], bf[nt][1]);
        }

        // refill stage for iteration kt+2 (after compute: 1-stage slack)
        if (tid == 0 && kt + STAGES - 1 < KITERS) {
            const int f  = kt + STAGES - 1;
            const int n  = f / 3;                      // fill instance
            const int ns = f - n * 3;                  // f % 3
            if (n >= 1)
                MBAR_WAIT_RELAXED(EMPTB + 8 * ns, (uint32_t)((n - 1) & 1));
            MBAR_EXPECT_TX(FULLB + 8 * ns, (uint32_t)STAGE_BYTES);
            const uint32_t tb = TILES + ns * STAGE_BYTES;
            const int kx = f * 64;
            TMA_LOAD_2D(tb,         &tma_a, kx, gm, FULLB + 8 * ns);
            TMA_LOAD_2D(tb + A_STG, &tma_b, kx, gn, FULLB + 8 * ns);
        }

        if (++cs == STAGES) { cs = 0; cph ^= 1; }
    }

    // ---- epilogue: streaming stores (no L2 pollution of A/B tiles) ----
    const int rbase = gm + wm * 64 + (lane >> 2);
    const int cbase = gn + wn * 64 + (lane & 3) * 2;
    #pragma unroll
    for (int mt = 0; mt < 4; mt++) {
        const int r0 = rbase + mt * 16;
        #pragma unroll
        for (int nt = 0; nt < 8; nt++) {
            const int c = cbase + nt * 8;
            STG_CS_V2(out + (size_t)r0 * N_TOTAL + c,
                      acc[mt][nt][0], acc[mt][nt][1]);
            STG_CS_V2(out + (size_t)(r0 + 8) * N_TOTAL + c,
                      acc[mt][nt][2], acc[mt][nt][3]);
        }
    }
}

// ------------------------------- host side ---------------------------------
typedef CUresult (*encode_fn_t)(CUtensorMap*, CUtensorMapDataType, cuuint32_t,
                                void*, const cuuint64_t*, const cuuint64_t*,
                                const cuuint32_t*, const cuuint32_t*,
                                CUtensorMapInterleave, CUtensorMapSwizzle,
                                CUtensorMapL2promotion, CUtensorMapFloatOOBfill);

static void make_map_f16(CUtensorMap* m, void* ptr,
                         uint64_t inner, uint64_t outer,
                         uint32_t box_i, uint32_t box_o) {
    encode_fn_t fn = nullptr;
    cudaDriverEntryPointQueryResult st;
    cudaGetDriverEntryPointByVersion("cuTensorMapEncodeTiled", (void**)&fn,
                                     12000, cudaEnableDefault, &st);
    if (!fn) return;
    cuuint64_t dims[2]    = {inner, outer};
    cuuint64_t strides[1] = {inner * 2};      // bytes (fp16)
    cuuint32_t box[2]     = {box_i, box_o};
    cuuint32_t es[2]      = {1, 1};
    fn(m, CU_TENSOR_MAP_DATA_TYPE_UINT16, 2, ptr, dims, strides, box, es,
       CU_TENSOR_MAP_INTERLEAVE_NONE, CU_TENSOR_MAP_SWIZZLE_128B,
       CU_TENSOR_MAP_L2_PROMOTION_L2_128B, CU_TENSOR_MAP_FLOAT_OOB_FILL_NONE);
}

extern "C" void kernel_launch(void* const* d_in, const int* in_sizes, int n_in,
                              void* d_out, int out_size) {
    const float* x = (const float*)d_in[0];   // [2,4096,4096]
    const float* w = (const float*)d_in[1];   // [16384,4096]
    float* out = (float*)d_out;               // [2,4096,16384]

    // fused prologue (1 launch so ncu -s5 -c1 lands on the GEMM)
    {
        const int n4x = (M_TOTAL * K_TOTAL) / 4;
        prep_kernel<<<(n4x + 255) / 256, 256>>>((const float4*)x,
                                                (const float4*)w, n4x);
    }

    void *p_a = nullptr, *p_b = nullptr;
    cudaGetSymbolAddress(&p_a, g_A);
    cudaGetSymbolAddress(&p_b, g_B);

    CUtensorMap mA, mB;
    make_map_f16(&mA, p_a, K_TOTAL, M_TOTAL, 64, 128);
    make_map_f16(&mB, p_b, K_TOTAL, N_TOTAL, 64, 128);

    cudaFuncSetAttribute(ternary_gemm_kernel,
                         cudaFuncAttributeMaxDynamicSharedMemorySize, SMEM_DYN);

    const int grid = (M_TOTAL / 128) * (N_TOTAL / 128);   // 64 * 128 = 8192
    ternary_gemm_kernel<<<grid, 128, SMEM_DYN>>>(mA, mB, out);
}

// round 15
// speedup vs baseline: 1.0683x; 1.0001x over previous
#include <cuda_runtime.h>
#include <cuda.h>
#include <cuda_fp16.h>
#include <cstdint>

// ============================================================================
// TernaryLinear: out[m,n] = sum_k x[m,k] * sign(w[n,k])
//   M = 8192, N = 16384, K = 4096, fp32 in/out.
//
// fp16 single-plane GEMM on legacy mma.sync (tcgen05 unavailable: harness
// emits plain compute_103 PTX). A = fp16(x), B = sign(w) exact in fp16,
// fp32 accumulation. rel_err ~2-3e-4 (verified rounds 4-14).
//
// Round-15 vs round 14 (best, 2.056 ms, tensor=91.6%, 2 CTA/SM):
//   * co-resident CTAs rotate their per-stage k-chunk order by blockIdx
//     parity (rot = 2): SMSP-sharing warp pairs (CTA0.wi, CTA1.wi) stop
//     firing LDSM bursts in lockstep, so one warp's MMAs cover the other's
//     LDSM window. Only change — everything else R14 verbatim.
// ============================================================================

#define M_TOTAL 8192
#define K_TOTAL 4096
#define N_TOTAL 16384

// ------------------------- device scratch (no mallocs) ---------------------
__device__ __align__(1024) __half g_A[(size_t)M_TOTAL * K_TOTAL];   // 64 MB
__device__ __align__(1024) __half g_B[(size_t)N_TOTAL * K_TOTAL];   // 128 MB

// ------------------------------ PTX helpers --------------------------------
__device__ __forceinline__ uint32_t smem_u32(const void* p) {
    uint32_t a;
    asm("{ .reg .u64 t; cvta.to.shared.u64 t, %1; cvt.u32.u64 %0, t; }"
        : "=r"(a) : "l"(p));
    return a;
}

#define MBAR_INIT(addr, cnt) \
    asm volatile("mbarrier.init.shared.b64 [%0], %1;" :: "r"(addr), "r"(cnt) : "memory")

#define MBAR_EXPECT_TX(addr, bytes) \
    asm volatile("mbarrier.arrive.expect_tx.shared.b64 _, [%0], %1;" \
                 :: "r"(addr), "r"(bytes) : "memory")

#define MBAR_ARRIVE(addr) \
    asm volatile("mbarrier.arrive.shared.b64 _, [%0];" :: "r"(addr) : "memory")

#define MBAR_WAIT(addr, ph) do {                                              \
    asm volatile("{\n\t.reg .pred P1;\n\t"                                    \
        "WAIT_%=:\n\t"                                                        \
        "mbarrier.try_wait.parity.acquire.cta.shared::cta.b64 P1, [%0], %1, 0x989680;\n\t" \
        "@P1 bra.uni DONE_%=;\n\t"                                            \
        "bra.uni WAIT_%=;\n\t"                                                \
        "DONE_%=:\n\t}"                                                       \
        :: "r"(addr), "r"(ph) : "memory");                                    \
} while (0)

// relaxed: post-wait accesses are async-proxy (TMA) only
#define MBAR_WAIT_RELAXED(addr, ph) do {                                      \
    asm volatile("{\n\t.reg .pred P1;\n\t"                                    \
        "WAIT_%=:\n\t"                                                        \
        "mbarrier.try_wait.parity.relaxed.cta.shared::cta.b64 P1, [%0], %1, 0x989680;\n\t" \
        "@P1 bra.uni DONE_%=;\n\t"                                            \
        "bra.uni WAIT_%=;\n\t"                                                \
        "DONE_%=:\n\t}"                                                       \
        :: "r"(addr), "r"(ph) : "memory");                                    \
} while (0)

#define TMA_LOAD_2D(dst, map, cx, cy, mbar) \
    asm volatile("cp.async.bulk.tensor.2d.shared::cta.global.tile.mbarrier::complete_tx::bytes " \
                 "[%0], [%1, {%2, %3}], [%4];" \
                 :: "r"(dst), "l"(map), "r"(cx), "r"(cy), "r"(mbar) : "memory")

#define FENCE_PROXY_ASYNC() \
    asm volatile("fence.proxy.async.shared::cta;" ::: "memory")

#define LDSM4(r0, r1, r2, r3, addr)                                           \
    asm volatile("ldmatrix.sync.aligned.m8n8.x4.shared.b16 {%0,%1,%2,%3}, [%4];" \
        : "=r"(r0), "=r"(r1), "=r"(r2), "=r"(r3) : "r"(addr))

#define MMA_F16(d, a, b0, b1)                                                 \
    asm volatile("mma.sync.aligned.m16n8k16.row.col.f32.f16.f16.f32 "         \
        "{%0,%1,%2,%3}, {%4,%5,%6,%7}, {%8,%9}, {%0,%1,%2,%3};"               \
        : "+f"((d)[0]), "+f"((d)[1]), "+f"((d)[2]), "+f"((d)[3])              \
        : "r"((a)[0]), "r"((a)[1]), "r"((a)[2]), "r"((a)[3]),                 \
          "r"(b0), "r"(b1))

// streaming (evict-first) 8-byte store
#define STG_CS_V2(ptr, v0, v1) \
    asm volatile("st.global.cs.v2.f32 [%0], {%1, %2};" \
                 :: "l"(ptr), "f"(v0), "f"(v1) : "memory")

// -------------------- fused prologue: x->fp16, sign(w)->fp16 ---------------
// sign() as fp16 bits: +1 = 0x3C00, -1 = 0xBC00, 0 = 0x0000
__device__ __forceinline__ uint32_t sgnh2(float a, float b) {
    uint32_t ua = __float_as_uint(a), ub = __float_as_uint(b);
    uint32_t ma = (a != 0.0f) ? 0x3C00u : 0u;
    uint32_t mb = (b != 0.0f) ? 0x3C00u : 0u;
    ma |= (ua >> 16) & 0x8000u;
    mb |= (ub >> 16) & 0x8000u;
    return ma | (mb << 16);
}

// one thread: 1 float4 of x (-> 8B of A) + 2 float4 of w (-> 16B of B)
__global__ void prep_kernel(const float4* __restrict__ x,
                            const float4* __restrict__ w, int n4x) {
    int i = blockIdx.x * blockDim.x + threadIdx.x;
    if (i >= n4x) return;

    float4 v = x[i];
    __half2 h0 = __floats2half2_rn(v.x, v.y);
    __half2 h1 = __floats2half2_rn(v.z, v.w);
    uint2 pa;
    pa.x = *reinterpret_cast<uint32_t*>(&h0);
    pa.y = *reinterpret_cast<uint32_t*>(&h1);
    reinterpret_cast<uint2*>(g_A)[i] = pa;

    float4 wa = w[2 * i];
    float4 wb = w[2 * i + 1];
    uint4 pb;
    pb.x = sgnh2(wa.x, wa.y);
    pb.y = sgnh2(wa.z, wa.w);
    pb.z = sgnh2(wb.x, wb.y);
    pb.w = sgnh2(wb.z, wb.w);
    reinterpret_cast<uint4*>(g_B)[i] = pb;
}

// ------------------------------- GEMM kernel -------------------------------
// CTA tile 128(M) x 128(N), K-step 64 halves (128 B rows). 3-stage TMA ring
// (32 KB/stage), FULL (tx) + EMPTY (4 warp arrivals) barriers.
// 128 threads = 4 warps (2x2); warp tile 64x64, 128 f32 accs / thread.
// 2 CTAs per SM; co-resident CTAs rotate chunk order by blockIdx parity.

static constexpr int STAGES      = 3;
static constexpr int A_STG       = 16384;           // 128 rows x 128 B
static constexpr int B_STG       = 16384;           // 128 rows x 128 B
static constexpr int STAGE_BYTES = A_STG + B_STG;   // 32 KB
static constexpr int KITERS      = K_TOTAL / 64;    // 64
static constexpr int SMEM_DYN    = 1024 + 1024 + STAGES * STAGE_BYTES;  // ~100KB

__global__ void __launch_bounds__(128, 2) ternary_gemm_kernel(
    const __grid_constant__ CUtensorMap tma_a,
    const __grid_constant__ CUtensorMap tma_b,
    float* __restrict__ out)
{
    extern __shared__ uint8_t smem_raw[];
    const uint32_t sb    = smem_u32(smem_raw);
    const uint32_t base  = (sb + 1023u) & ~1023u;
    const uint32_t FULLB = base;          // 3 x 8B
    const uint32_t EMPTB = base + 64;     // 3 x 8B
    const uint32_t TILES = base + 1024;

    const int tid  = threadIdx.x;
    const int wid  = tid >> 5;
    const int lane = tid & 31;
    const int wm   = wid >> 1;            // 0..1  (M)
    const int wn   = wid & 1;             // 0..1  (N)
    const int rot  = (int)(blockIdx.x & 1) * 2;   // chunk-order rotation

    // ---- tile mapping, GROUP_M=16 for L2 reuse ----
    constexpr int TILES_N = N_TOTAL / 128;   // 128
    constexpr int GROUP_M = 16;              // of 64 M-tiles
    const int per_group = GROUP_M * TILES_N;
    const int grp = blockIdx.x / per_group;
    const int ing = blockIdx.x % per_group;
    const int gm = (grp * GROUP_M + (ing % GROUP_M)) * 128;
    const int gn = (ing / GROUP_M) * 128;

    // ---- init barriers ----
    if (tid == 0) {
        #pragma unroll
        for (int s = 0; s < STAGES; s++) {
            MBAR_INIT(FULLB + 8 * s, 1);
            MBAR_INIT(EMPTB + 8 * s, 4);       // 4 warps arrive
        }
        FENCE_PROXY_ASYNC();
    }
    __syncthreads();   // only CTA-wide barrier in the kernel

    // ---- prologue: fill stages 0..1 (first fills, no EMPTY wait) ----
    if (tid == 0) {
        #pragma unroll
        for (int s = 0; s < STAGES - 1; s++) {
            MBAR_EXPECT_TX(FULLB + 8 * s, (uint32_t)STAGE_BYTES);
            const uint32_t tb = TILES + s * STAGE_BYTES;
            TMA_LOAD_2D(tb,         &tma_a, s * 64, gm, FULLB + 8 * s);
            TMA_LOAD_2D(tb + A_STG, &tma_b, s * 64, gn, FULLB + 8 * s);
        }
    }

    // ---- per-lane ldmatrix address pieces (SW128 layout, verified R2-R14) --
    const int mi  = lane >> 3;
    const int r   = lane & 7;
    const int hi2 = mi >> 1;
    const uint32_t a_row_off = (uint32_t)(wm * 64 + (mi & 1) * 8 + r) * 128;
    const uint32_t b_row_off = (uint32_t)(wn * 64 + hi2 * 8 + r) * 128;

    // ---- accumulators: [mt(4)][nt(8)][4] f32 = 128 regs ----
    float acc[4][8][4];
    #pragma unroll
    for (int a = 0; a < 4; a++)
        #pragma unroll
        for (int b = 0; b < 8; b++)
            #pragma unroll
            for (int c = 0; c < 4; c++) acc[a][b][c] = 0.0f;

    // ---- main loop (stage cursor: modulo-3 wrap) ----
    int cs = 0;                 // consumer stage
    uint32_t cph = 0;           // consumer phase

    for (int kt = 0; kt < KITERS; kt++) {
        MBAR_WAIT(FULLB + 8 * cs, cph);

        const uint32_t sa  = TILES + cs * STAGE_BYTES;
        const uint32_t sbb = sa + A_STG;

        #pragma unroll
        for (int kc = 0; kc < 4; kc++) {   // 4 x k16 per 128B chunk
            const int kcc = (kc + rot) & 3;   // CTA-parity rotated order
            const uint32_t ax = (uint32_t)((((kcc << 1) | hi2) ^ r) << 4);
            const uint32_t bx = (uint32_t)((((kcc << 1) | (mi & 1)) ^ r) << 4);

            uint32_t af[4][4], bf[8][2];
            #pragma unroll
            for (int mt = 0; mt < 4; mt++)
                LDSM4(af[mt][0], af[mt][1], af[mt][2], af[mt][3],
                      sa + a_row_off + mt * 2048 + ax);
            #pragma unroll
            for (int j = 0; j < 4; j++)
                LDSM4(bf[2 * j][0], bf[2 * j][1], bf[2 * j + 1][0], bf[2 * j + 1][1],
                      sbb + b_row_off + j * 2048 + bx);

            // stage data fully in registers after the last ldmatrix
            if (kc == 3 && lane == 0) MBAR_ARRIVE(EMPTB + 8 * cs);

            #pragma unroll
            for (int mt = 0; mt < 4; mt++)
                #pragma unroll
                for (int nt = 0; nt < 8; nt++)
                    MMA_F16(acc[mt][nt], af[mt], bf[nt][0], bf[nt][1]);
        }

        // refill stage for iteration kt+2 (after compute: 1-stage slack)
        if (tid == 0 && kt + STAGES - 1 < KITERS) {
            const int f  = kt + STAGES - 1;
            const int n  = f / 3;                      // fill instance
            const int ns = f - n * 3;                  // f % 3
            if (n >= 1)
                MBAR_WAIT_RELAXED(EMPTB + 8 * ns, (uint32_t)((n - 1) & 1));
            MBAR_EXPECT_TX(FULLB + 8 * ns, (uint32_t)STAGE_BYTES);
            const uint32_t tb = TILES + ns * STAGE_BYTES;
            const int kx = f * 64;
            TMA_LOAD_2D(tb,         &tma_a, kx, gm, FULLB + 8 * ns);
            TMA_LOAD_2D(tb + A_STG, &tma_b, kx, gn, FULLB + 8 * ns);
        }

        if (++cs == STAGES) { cs = 0; cph ^= 1; }
    }

    // ---- epilogue: streaming stores ----
    const int rbase = gm + wm * 64 + (lane >> 2);
    const int cbase = gn + wn * 64 + (lane & 3) * 2;
    #pragma unroll
    for (int mt = 0; mt < 4; mt++) {
        const int r0 = rbase + mt * 16;
        #pragma unroll
        for (int nt = 0; nt < 8; nt++) {
            const int c = cbase + nt * 8;
            STG_CS_V2(out + (size_t)r0 * N_TOTAL + c,
                      acc[mt][nt][0], acc[mt][nt][1]);
            STG_CS_V2(out + (size_t)(r0 + 8) * N_TOTAL + c,
                      acc[mt][nt][2], acc[mt][nt][3]);
        }
    }
}

// ------------------------------- host side ---------------------------------
typedef CUresult (*encode_fn_t)(CUtensorMap*, CUtensorMapDataType, cuuint32_t,
                                void*, const cuuint64_t*, const cuuint64_t*,
                                const cuuint32_t*, const cuuint32_t*,
                                CUtensorMapInterleave, CUtensorMapSwizzle,
                                CUtensorMapL2promotion, CUtensorMapFloatOOBfill);

static void make_map_f16(CUtensorMap* m, void* ptr,
                         uint64_t inner, uint64_t outer,
                         uint32_t box_i, uint32_t box_o) {
    encode_fn_t fn = nullptr;
    cudaDriverEntryPointQueryResult st;
    cudaGetDriverEntryPointByVersion("cuTensorMapEncodeTiled", (void**)&fn,
                                     12000, cudaEnableDefault, &st);
    if (!fn) return;
    cuuint64_t dims[2]    = {inner, outer};
    cuuint64_t strides[1] = {inner * 2};      // bytes (fp16)
    cuuint32_t box[2]     = {box_i, box_o};
    cuuint32_t es[2]      = {1, 1};
    fn(m, CU_TENSOR_MAP_DATA_TYPE_UINT16, 2, ptr, dims, strides, box, es,
       CU_TENSOR_MAP_INTERLEAVE_NONE, CU_TENSOR_MAP_SWIZZLE_128B,
       CU_TENSOR_MAP_L2_PROMOTION_L2_128B, CU_TENSOR_MAP_FLOAT_OOB_FILL_NONE);
}

extern "C" void kernel_launch(void* const* d_in, const int* in_sizes, int n_in,
                              void* d_out, int out_size) {
    const float* x = (const float*)d_in[0];   // [2,4096,4096]
    const float* w = (const float*)d_in[1];   // [16384,4096]
    float* out = (float*)d_out;               // [2,4096,16384]

    // fused prologue (1 launch so ncu -s5 -c1 lands on the GEMM)
    {
        const int n4x = (M_TOTAL * K_TOTAL) / 4;
        prep_kernel<<<(n4x + 255) / 256, 256>>>((const float4*)x,
                                                (const float4*)w, n4x);
    }

    void *p_a = nullptr, *p_b = nullptr;
    cudaGetSymbolAddress(&p_a, g_A);
    cudaGetSymbolAddress(&p_b, g_B);

    CUtensorMap mA, mB;
    make_map_f16(&mA, p_a, K_TOTAL, M_TOTAL, 64, 128);
    make_map_f16(&mB, p_b, K_TOTAL, N_TOTAL, 64, 128);

    cudaFuncSetAttribute(ternary_gemm_kernel,
                         cudaFuncAttributeMaxDynamicSharedMemorySize, SMEM_DYN);

    const int grid = (M_TOTAL / 128) * (N_TOTAL / 128);   // 64 * 128 = 8192
    ternary_gemm_kernel<<<grid, 128, SMEM_DYN>>>(mA, mB, out);
}